// round 7
// baseline (speedup 1.0000x reference)
#include <cuda_runtime.h>
#include <cuda_bf16.h>
#include <math.h>
#include <stdint.h>

#define B_  32
#define S_  128
#define E_  512
#define H_  512
#define V_  32000
#define G3  1536   // 3*H

// ---------------------------------------------------------------------------
// Scratch (__device__ globals: no allocations allowed)
// ---------------------------------------------------------------------------
__device__ __align__(16) float g_xgates[S_ * G3 * B_];            // [s][g][b]
__device__ __align__(16) __nv_bfloat16 g_hs_hi[B_ * S_ * H_];     // [b][s][h] -> row m=b*S+s
__device__ __align__(16) __nv_bfloat16 g_hs_lo[B_ * S_ * H_];
__device__ __align__(16) __nv_bfloat16 g_wout_hi[(size_t)V_ * H_];
__device__ __align__(16) __nv_bfloat16 g_wout_lo[(size_t)V_ * H_];
__device__ __align__(16) float g_h[2][B_ * H_];                   // [b][k]
__device__ unsigned long long g_bar = 0ULL;

// ---------------------------------------------------------------------------
// w_out fp32 -> bf16 hi/lo split
// ---------------------------------------------------------------------------
__global__ void __launch_bounds__(256) convert_wout_kernel(const float* __restrict__ w) {
    size_t i = (size_t)blockIdx.x * 256 + threadIdx.x;      // float4 index
    const float4* w4 = (const float4*)w;
    float4 v = w4[i];
    __nv_bfloat16 h0 = __float2bfloat16(v.x);
    __nv_bfloat16 h1 = __float2bfloat16(v.y);
    __nv_bfloat16 h2 = __float2bfloat16(v.z);
    __nv_bfloat16 h3 = __float2bfloat16(v.w);
    __nv_bfloat16 l0 = __float2bfloat16(v.x - __bfloat162float(h0));
    __nv_bfloat16 l1 = __float2bfloat16(v.y - __bfloat162float(h1));
    __nv_bfloat16 l2 = __float2bfloat16(v.z - __bfloat162float(h2));
    __nv_bfloat16 l3 = __float2bfloat16(v.w - __bfloat162float(h3));
    ((__nv_bfloat162*)g_wout_hi)[i * 2 + 0] = __nv_bfloat162(h0, h1);
    ((__nv_bfloat162*)g_wout_hi)[i * 2 + 1] = __nv_bfloat162(h2, h3);
    ((__nv_bfloat162*)g_wout_lo)[i * 2 + 0] = __nv_bfloat162(l0, l1);
    ((__nv_bfloat162*)g_wout_lo)[i * 2 + 1] = __nv_bfloat162(l2, l3);
}

// ---------------------------------------------------------------------------
// Gates GEMM: x_gates[s][g][b] = embed_x @ w_ih^T + b_ih
// Tile rows use m' = s*32 + b so the epilogue writes coalesced float4s
// along b into [s][g][b].
// ---------------------------------------------------------------------------
__global__ void __launch_bounds__(256) gemm_gates_kernel(
    const float* __restrict__ A,
    const float* __restrict__ Bm,
    const float* __restrict__ bias)
{
    __shared__ float As[8][128];
    __shared__ float Bs[8][128];

    const int t     = threadIdx.x;
    const int mBase = blockIdx.y * 128;     // m' tile base
    const int nBase = blockIdx.x * 128;
    const int ty    = t >> 4;
    const int tx    = t & 15;
    const int lrow  = t >> 1;
    const int lq    = (t & 1) * 4;

    // m' = s*32 + b  ->  gmem row = b*S + s
    const int mprow = mBase + lrow;
    const int arow  = (mprow & 31) * S_ + (mprow >> 5);

    const float* Ab = A  + (size_t)arow * E_ + lq;
    const float* Bb = Bm + (size_t)(nBase + lrow) * E_ + lq;

    float acc[8][8];
#pragma unroll
    for (int i = 0; i < 8; i++)
#pragma unroll
        for (int j = 0; j < 8; j++) acc[i][j] = 0.f;

    for (int k0 = 0; k0 < E_; k0 += 8) {
        float4 av = *(const float4*)(Ab + k0);
        float4 bv = *(const float4*)(Bb + k0);
        __syncthreads();
        As[lq + 0][lrow] = av.x; As[lq + 1][lrow] = av.y;
        As[lq + 2][lrow] = av.z; As[lq + 3][lrow] = av.w;
        Bs[lq + 0][lrow] = bv.x; Bs[lq + 1][lrow] = bv.y;
        Bs[lq + 2][lrow] = bv.z; Bs[lq + 3][lrow] = bv.w;
        __syncthreads();

#pragma unroll
        for (int k = 0; k < 8; k++) {
            float ra[8], rb[8];
            *(float4*)(ra + 0) = *(const float4*)&As[k][ty * 8 + 0];
            *(float4*)(ra + 4) = *(const float4*)&As[k][ty * 8 + 4];
            *(float4*)(rb + 0) = *(const float4*)&Bs[k][tx * 8 + 0];
            *(float4*)(rb + 4) = *(const float4*)&Bs[k][tx * 8 + 4];
#pragma unroll
            for (int i = 0; i < 8; i++)
#pragma unroll
                for (int j = 0; j < 8; j++)
                    acc[i][j] += ra[i] * rb[j];
        }
    }

    // epilogue: thread rows = 8 consecutive b within one s (ty*8 aligned)
    const int mp0 = mBase + ty * 8;
    const int sG  = mp0 >> 5;
    const int b0  = mp0 & 31;
#pragma unroll
    for (int j = 0; j < 8; j++) {
        int g = nBase + tx * 8 + j;
        float bj = bias[g];
        float* dst = g_xgates + ((size_t)sG * G3 + g) * B_ + b0;
        float4 v0, v1;
        v0.x = acc[0][j] + bj; v0.y = acc[1][j] + bj;
        v0.z = acc[2][j] + bj; v0.w = acc[3][j] + bj;
        v1.x = acc[4][j] + bj; v1.y = acc[5][j] + bj;
        v1.z = acc[6][j] + bj; v1.w = acc[7][j] + bj;
        *(float4*)(dst + 0) = v0;
        *(float4*)(dst + 4) = v1;
    }
}

// ---------------------------------------------------------------------------
// Persistent GRU scan, shfl-reduced. 128 blocks x 512 threads.
// Warp w: jl = w&3 (j column), boct = w>>2. Lane: bo = lane&7, ks = lane>>3.
// Thread (b = boct*8+bo, ks, jl) does k-chunk [ks*128, +128); butterfly
// shfl over lane bits 3,4 reduces ks; lanes ks==0 do gate math inline.
// ---------------------------------------------------------------------------
#define SH_PAD   4
#define SH_LDK   (H_ + SH_PAD)            // 516
#define WS_FLTS  (4 * 3 * H_)             // 6144
#define SH_FLTS  (B_ * SH_LDK)            // 16512
#define PERS_SMEM ((WS_FLTS + SH_FLTS) * (int)sizeof(float))

__device__ __forceinline__ void grid_barrier() {
    __syncthreads();
    if (threadIdx.x == 0) {
        __threadfence();
        unsigned long long ticket = atomicAdd(&g_bar, 1ULL);
        unsigned long long target = (ticket - (ticket & 127ULL)) + 128ULL;
        unsigned long long v;
        unsigned int guard = 0;
        do {
            asm volatile("ld.global.acquire.gpu.u64 %0, [%1];"
                         : "=l"(v) : "l"(&g_bar));
        } while (v < target && (++guard < (1u << 22)));
    }
    __syncthreads();
}

__global__ void __launch_bounds__(512) gru_scan_kernel(
    const float* __restrict__ hidden,
    const float* __restrict__ w_hh,
    const float* __restrict__ b_hh)
{
    extern __shared__ float sm[];
    float* ws = sm;                 // [jl][g][k] : (jl*3+g)*512 + k
    float* sh = sm + WS_FLTS;       // [b][k+pad] : b*516 + k

    float4* ws4 = (float4*)ws;
    float4* sh4 = (float4*)sh;      // b stride = 129 float4

    const int t    = threadIdx.x;
    const int blk  = blockIdx.x;
    const int lane = t & 31;
    const int w    = t >> 5;
    const int jl   = w & 3;
    const int boct = w >> 2;
    const int bo   = lane & 7;
    const int ks   = lane >> 3;
    const int b    = boct * 8 + bo;
    const int jg   = blk * 4 + jl;

    // one-time: stage w_hh slice (cols 4*blk..4*blk+3, 3 gates)
    {
        const float4* w4 = (const float4*)w_hh;
        for (int idx = t; idx < WS_FLTS / 4; idx += 512) {
            int jj  = idx / 384;
            int rem = idx - jj * 384;
            int g   = rem >> 7;
            int kq  = rem & 127;
            ws4[idx] = w4[(size_t)(g * H_ + blk * 4 + jj) * 128 + kq];
        }
    }
    // one-time: init g_h[0] = hidden ([b][k] layout)
    {
        int idx = blk * 512 + t;
        if (idx < (B_ * H_) / 4)
            ((float4*)g_h[0])[idx] = ((const float4*)hidden)[idx];
    }
    grid_barrier();

    const float bhr = b_hh[jg];
    const float bhz = b_hh[H_ + jg];
    const float bhn = b_hh[2 * H_ + jg];

    const float4* hp0 = sh4 + b * (SH_LDK / 4) + ks * 32;
    const float4* wr0 = ws4 + (jl * 3 + 0) * 128 + ks * 32;
    const float4* wz0 = ws4 + (jl * 3 + 1) * 128 + ks * 32;
    const float4* wn0 = ws4 + (jl * 3 + 2) * 128 + ks * 32;

    for (int s = 0; s < S_; s++) {
        const int p = s & 1;

        // prefetch x-gates early (independent of h)
        const float* xg = g_xgates + (size_t)s * G3 * B_;
        float xr = xg[(size_t)(jg)          * B_ + b];
        float xz = xg[(size_t)(H_ + jg)     * B_ + b];
        float xn = xg[(size_t)(2 * H_ + jg) * B_ + b];

        // stage h[p] (gmem [b][k]) -> smem [b][k+pad]
        {
            const float4* src = (const float4*)g_h[p];
            for (int i = t; i < (B_ * H_) / 4; i += 512) {
                int bb = i >> 7;
                int kq = i & 127;
                sh4[bb * (SH_LDK / 4) + kq] = src[i];
            }
        }
        __syncthreads();

        // dot products over this thread's k-chunk
        float ar = 0.f, az = 0.f, an = 0.f;
#pragma unroll
        for (int kk = 0; kk < 32; kk++) {
            float4 h4 = hp0[kk];
            float4 r4 = wr0[kk];
            float4 z4 = wz0[kk];
            float4 n4 = wn0[kk];
            ar += h4.x * r4.x; ar += h4.y * r4.y; ar += h4.z * r4.z; ar += h4.w * r4.w;
            az += h4.x * z4.x; az += h4.y * z4.y; az += h4.z * z4.z; az += h4.w * z4.w;
            an += h4.x * n4.x; an += h4.y * n4.y; an += h4.z * n4.z; an += h4.w * n4.w;
        }
        // butterfly reduce over ks (lane bits 3,4)
        ar += __shfl_xor_sync(0xffffffffu, ar, 16);
        az += __shfl_xor_sync(0xffffffffu, az, 16);
        an += __shfl_xor_sync(0xffffffffu, an, 16);
        ar += __shfl_xor_sync(0xffffffffu, ar, 8);
        az += __shfl_xor_sync(0xffffffffu, az, 8);
        an += __shfl_xor_sync(0xffffffffu, an, 8);

        if (ks == 0) {
            float r = 1.f / (1.f + expf(-(xr + ar + bhr)));
            float z = 1.f / (1.f + expf(-(xz + az + bhz)));
            float n = tanhf(xn + r * (an + bhn));
            float hold = sh[b * SH_LDK + jg];
            float hnew = (1.f - z) * n + z * hold;

            g_h[p ^ 1][b * H_ + jg] = hnew;

            size_t oi = ((size_t)b * S_ + s) * H_ + jg;
            __nv_bfloat16 hi = __float2bfloat16(hnew);
            g_hs_hi[oi] = hi;
            g_hs_lo[oi] = __float2bfloat16(hnew - __bfloat162float(hi));
        }

        if (s < S_ - 1) grid_barrier();
        else __syncthreads();
    }
}

// ---------------------------------------------------------------------------
// Projection via warp-level mma.sync (HMMA bf16, fp32 accum), 3-term split.
// 128x128 tile/CTA, 8 warps (2x4 of 64x32), BK=32, cp.async double buffer.
// ---------------------------------------------------------------------------
#define PROJ_PITCH_B 80
#define PROJ_TILE_B  (128 * PROJ_PITCH_B)
#define PROJ_BUF_B   (4 * PROJ_TILE_B)
#define PROJ_SMEM    (2 * PROJ_BUF_B)
#define KCH 16

__device__ __forceinline__ uint32_t smem_u32(const void* p) {
    uint32_t a;
    asm("{ .reg .u64 tmp; cvta.to.shared.u64 tmp, %1; cvt.u32.u64 %0, tmp; }"
        : "=r"(a) : "l"(p));
    return a;
}
__device__ __forceinline__ void cp_async16(uint32_t saddr, const void* gaddr) {
    asm volatile("cp.async.cg.shared.global [%0], [%1], 16;" :: "r"(saddr), "l"(gaddr));
}
__device__ __forceinline__ void ldm_x4(uint32_t* r, uint32_t addr) {
    asm volatile("ldmatrix.sync.aligned.m8n8.x4.shared.b16 {%0,%1,%2,%3}, [%4];"
                 : "=r"(r[0]), "=r"(r[1]), "=r"(r[2]), "=r"(r[3]) : "r"(addr));
}
__device__ __forceinline__ void ldm_x2(uint32_t* r, uint32_t addr) {
    asm volatile("ldmatrix.sync.aligned.m8n8.x2.shared.b16 {%0,%1}, [%2];"
                 : "=r"(r[0]), "=r"(r[1]) : "r"(addr));
}
__device__ __forceinline__ void mma16816(float* c, const uint32_t* a, const uint32_t* b) {
    asm volatile(
        "mma.sync.aligned.m16n8k16.row.col.f32.bf16.bf16.f32 "
        "{%0,%1,%2,%3}, {%4,%5,%6,%7}, {%8,%9}, {%0,%1,%2,%3};"
        : "+f"(c[0]), "+f"(c[1]), "+f"(c[2]), "+f"(c[3])
        : "r"(a[0]), "r"(a[1]), "r"(a[2]), "r"(a[3]), "r"(b[0]), "r"(b[1]));
}

__device__ __forceinline__ void proj_prefetch(
    uint32_t sbase, int buf, int kc, int mBase, int nBase, int t)
{
    uint32_t bb = sbase + (uint32_t)buf * PROJ_BUF_B;
#pragma unroll
    for (int i = 0; i < 2; i++) {
        int idx = t + i * 256;
        int row = idx >> 2;
        int q   = idx & 3;
        size_t gA = (size_t)(mBase + row) * H_ + kc * 32 + q * 8;
        size_t gB = (size_t)(nBase + row) * H_ + kc * 32 + q * 8;
        uint32_t so = (uint32_t)(row * PROJ_PITCH_B + q * 16);
        cp_async16(bb + 0 * PROJ_TILE_B + so, g_hs_hi + gA);
        cp_async16(bb + 1 * PROJ_TILE_B + so, g_hs_lo + gA);
        cp_async16(bb + 2 * PROJ_TILE_B + so, g_wout_hi + gB);
        cp_async16(bb + 3 * PROJ_TILE_B + so, g_wout_lo + gB);
    }
}

__global__ void __launch_bounds__(256, 1) proj_mma_kernel(float* __restrict__ out)
{
    extern __shared__ __align__(128) char smem[];
    const uint32_t sbase = smem_u32(smem);

    const int t    = threadIdx.x;
    const int wid  = t >> 5;
    const int lane = t & 31;
    const int wm   = wid >> 2;
    const int wn   = wid & 3;
    const int mBase = blockIdx.x * 128;
    const int nBase = blockIdx.y * 128;

    float acc[4][4][4];
#pragma unroll
    for (int i = 0; i < 4; i++)
#pragma unroll
        for (int j = 0; j < 4; j++)
#pragma unroll
            for (int q = 0; q < 4; q++) acc[i][j][q] = 0.f;

    proj_prefetch(sbase, 0, 0, mBase, nBase, t);
    asm volatile("cp.async.commit_group;" ::: "memory");

    int buf = 0;
    for (int kc = 0; kc < KCH; kc++) {
        __syncthreads();
        if (kc + 1 < KCH) {
            proj_prefetch(sbase, buf ^ 1, kc + 1, mBase, nBase, t);
            asm volatile("cp.async.commit_group;" ::: "memory");
            asm volatile("cp.async.wait_group 1;" ::: "memory");
        } else {
            asm volatile("cp.async.wait_group 0;" ::: "memory");
        }
        __syncthreads();

        const uint32_t bb = sbase + (uint32_t)buf * PROJ_BUF_B;
#pragma unroll
        for (int ks = 0; ks < 2; ks++) {
            uint32_t aH[4][4], aL[4][4], bH[4][2], bL[4][2];
            const int kbA = ks * 32 + (lane >> 4) * 16;
            const int kbB = ks * 32 + ((lane >> 3) & 1) * 16;
#pragma unroll
            for (int mf = 0; mf < 4; mf++) {
                uint32_t ar = bb + (uint32_t)((wm * 64 + mf * 16 + (lane & 15)) * PROJ_PITCH_B + kbA);
                ldm_x4(aH[mf], ar);
                ldm_x4(aL[mf], ar + PROJ_TILE_B);
            }
#pragma unroll
            for (int nf = 0; nf < 4; nf++) {
                uint32_t br = bb + 2 * PROJ_TILE_B +
                              (uint32_t)((wn * 32 + nf * 8 + (lane & 7)) * PROJ_PITCH_B + kbB);
                ldm_x2(bH[nf], br);
                ldm_x2(bL[nf], br + PROJ_TILE_B);
            }
#pragma unroll
            for (int mf = 0; mf < 4; mf++)
#pragma unroll
                for (int nf = 0; nf < 4; nf++) {
                    mma16816(acc[mf][nf], aH[mf], bH[nf]);
                    mma16816(acc[mf][nf], aH[mf], bL[nf]);
                    mma16816(acc[mf][nf], aL[mf], bH[nf]);
                }
        }
        buf ^= 1;
    }

    const int r0 = lane >> 2;
    const int c0 = (lane & 3) * 2;
#pragma unroll
    for (int mf = 0; mf < 4; mf++) {
#pragma unroll
        for (int nf = 0; nf < 4; nf++) {
            int m = mBase + wm * 64 + mf * 16 + r0;
            int n = nBase + wn * 32 + nf * 8 + c0;
            float* p0 = out + (size_t)m * V_ + n;
            float* p1 = out + (size_t)(m + 8) * V_ + n;
            *(float2*)p0 = make_float2(acc[mf][nf][0], acc[mf][nf][1]);
            *(float2*)p1 = make_float2(acc[mf][nf][2], acc[mf][nf][3]);
        }
    }
}

// ---------------------------------------------------------------------------
extern "C" void kernel_launch(void* const* d_in, const int* in_sizes, int n_in,
                              void* d_out, int out_size)
{
    const float* embed_x = (const float*)d_in[0];
    const float* hidden  = (const float*)d_in[1];
    const float* w_ih    = (const float*)d_in[2];
    const float* w_hh    = (const float*)d_in[3];
    const float* b_ih    = (const float*)d_in[4];
    const float* b_hh    = (const float*)d_in[5];
    const float* w_out   = (const float*)d_in[6];
    float* out = (float*)d_out;

    (void)in_sizes; (void)n_in; (void)out_size;

    cudaFuncSetAttribute(gru_scan_kernel,
                         cudaFuncAttributeMaxDynamicSharedMemorySize, PERS_SMEM);
    cudaFuncSetAttribute(proj_mma_kernel,
                         cudaFuncAttributeMaxDynamicSharedMemorySize, PROJ_SMEM);

    // 1) convert w_out to bf16 hi/lo
    convert_wout_kernel<<<((size_t)V_ * H_ / 4) / 256, 256>>>(w_out);

    // 2) gates GEMM: x_gates = embed_x @ w_ih^T + b_ih  -> [s][g][b]
    {
        dim3 grid(G3 / 128, (B_ * S_) / 128);   // (12, 32)
        gemm_gates_kernel<<<grid, 256>>>(embed_x, w_ih, b_ih);
    }

    // 3) persistent GRU scan (emits hs as bf16 hi/lo)
    gru_scan_kernel<<<H_ / 4, 512, PERS_SMEM>>>(hidden, w_hh, b_hh);

    // 4) projection via HMMA bf16-split
    {
        dim3 grid((B_ * S_) / 128, V_ / 128);   // (32, 250)
        proj_mma_kernel<<<grid, 256, PROJ_SMEM>>>(out);
    }
}